// round 4
// baseline (speedup 1.0000x reference)
#include <cuda_runtime.h>
#include <cstdint>

// LayerNorm backward fused: golden_x [B,S,H], golden_gamma [H], golden_beta [H]
// B=4, S=4096, H=2048, fp32. Output layout: [x | gamma | beta] concatenated.
// R3: cp.async 3-stage smem pipeline for dy/x1/x2 (2 rows in flight through
//     the barriers), register distance-1 prefetch for dsum/mean/rstd,
//     3 CTAs/SM (grid=444).

#define HF 2048
#define ROWS 16384           // B*S
#define THREADS 256
#define NCTA_SM 3
#define GRID (148 * NCTA_SM) // 444
#define NSTAGES 3
#define STAGE_FLOATS (3 * HF)              // dy, x1, x2 per stage
#define STAGE_BYTES (STAGE_FLOATS * 4)     // 24576
#define DYN_SMEM (NSTAGES * STAGE_BYTES)   // 73728

__global__ void zero_param_grads(float* __restrict__ out) {
    int i = blockIdx.x * blockDim.x + threadIdx.x;
    if (i < 2 * HF) out[(size_t)ROWS * HF + i] = 0.0f;
}

__device__ __forceinline__ void cp16(uint32_t dst, const void* src) {
    asm volatile("cp.async.cg.shared.global [%0], [%1], 16;\n"
                 :: "r"(dst), "l"(src));
}

__global__ __launch_bounds__(THREADS, NCTA_SM) void ln_bwd_kernel(
    const float* __restrict__ dy,
    const float* __restrict__ x1,
    const float* __restrict__ x2,
    const float* __restrict__ rstd,
    const float* __restrict__ mean,
    const float* __restrict__ gamma,
    const float* __restrict__ dsum,
    float* __restrict__ out)
{
    extern __shared__ float smem[];          // [NSTAGES][3][HF]
    __shared__ float red[2][3][8];           // parity-2 cross-warp reduction

    const int tid  = threadIdx.x;
    const int lane = tid & 31;
    const int wid  = tid >> 5;
    const int bid  = blockIdx.x;

    // Each thread owns 8 fixed columns: [c0..c0+3] and [c1..c1+3]
    const int c0 = 4 * tid;          // 0..1020
    const int c1 = c0 + HF / 2;      // 1024..2044

    const uint32_t smem_u32 = (uint32_t)__cvta_generic_to_shared(smem);

    // gamma: loaded once, register-resident across all rows
    const float4 g0 = *(const float4*)(gamma + c0);
    const float4 g1 = *(const float4*)(gamma + c1);
    float gv[8] = {g0.x, g0.y, g0.z, g0.w, g1.x, g1.y, g1.z, g1.w};

    // per-thread partial dgamma / dbeta accumulators (fixed column mapping)
    float ag[8] = {0.f, 0.f, 0.f, 0.f, 0.f, 0.f, 0.f, 0.f};
    float ab[8] = {0.f, 0.f, 0.f, 0.f, 0.f, 0.f, 0.f, 0.f};

    const float inv_d = 1.0f / (float)HF;

    // ---- cp.async stage issue: copy one row of dy/x1/x2 into a stage slot
    auto issue = [&](int slot, int row) {
        if (row < ROWS) {
            const size_t gb = (size_t)row * HF;
            const uint32_t db = smem_u32 + (uint32_t)slot * STAGE_BYTES + tid * 16;
            const char* s0 = (const char*)(dy + gb) + tid * 16;
            cp16(db,               s0);
            cp16(db + 4096,        s0 + 4096);
            const char* s1 = (const char*)(x1 + gb) + tid * 16;
            cp16(db + 8192,        s1);
            cp16(db + 8192 + 4096, s1 + 4096);
            const char* s2 = (const char*)(x2 + gb) + tid * 16;
            cp16(db + 16384,        s2);
            cp16(db + 16384 + 4096, s2 + 4096);
        }
        asm volatile("cp.async.commit_group;\n" ::: "memory");
    };

    // ---- pipeline prologue: 2 stages in flight ----
    issue(0, bid);
    issue(1, bid + GRID);

    // distance-1 register prefetch for dsum / mean / rstd (needed post-barrier)
    float4 Pd0 = __ldcs((const float4*)(dsum + (size_t)bid * HF + c0));
    float4 Pd1 = __ldcs((const float4*)(dsum + (size_t)bid * HF + c1));
    float  Pmu = mean[bid];
    float  Prs = rstd[bid];

    int i = 0;
    for (int row = bid; row < ROWS; row += GRID, ++i) {
        const int slot = i % NSTAGES;

        // issue stage i+2 first so its LDGSTS are in flight through everything
        issue((i + 2) % NSTAGES, row + 2 * GRID);

        asm volatile("cp.async.wait_group 2;\n" ::: "memory");
        __syncthreads();   // A: slot data visible to all threads

        const float* st = smem + slot * STAGE_FLOATS;
        const float4 dy0 = *(const float4*)(st + c0);
        const float4 dy1 = *(const float4*)(st + c1);
        const float4 a0  = *(const float4*)(st + HF + c0);
        const float4 a1  = *(const float4*)(st + HF + c1);
        const float4 b0  = *(const float4*)(st + 2 * HF + c0);
        const float4 b1  = *(const float4*)(st + 2 * HF + c1);

        const float mu = Pmu;
        const float rs = Prs;
        float dyv[8] = {dy0.x, dy0.y, dy0.z, dy0.w, dy1.x, dy1.y, dy1.z, dy1.w};
        float xh[8]  = {a0.x + b0.x - mu, a0.y + b0.y - mu,
                        a0.z + b0.z - mu, a0.w + b0.w - mu,
                        a1.x + b1.x - mu, a1.y + b1.y - mu,
                        a1.z + b1.z - mu, a1.w + b1.w - mu};
        float dsv[8] = {Pd0.x, Pd0.y, Pd0.z, Pd0.w, Pd1.x, Pd1.y, Pd1.z, Pd1.w};

        // prefetch next row's dsum/mean/rstd (consumed next iteration, post-barrier)
        const int nrow = row + GRID;
        if (nrow < ROWS) {
            const size_t nb = (size_t)nrow * HF;
            Pd0 = __ldcs((const float4*)(dsum + nb + c0));
            Pd1 = __ldcs((const float4*)(dsum + nb + c1));
            Pmu = mean[nrow];
            Prs = rstd[nrow];
        }

        // local partial sums
        float s1 = 0.f, s2 = 0.f, s3 = 0.f;
        #pragma unroll
        for (int k = 0; k < 8; k++) {
            const float pdxl = dyv[k] * gv[k];
            s1 = fmaf(pdxl, xh[k], s1);
            s2 += pdxl;
            s3 += xh[k];
        }

        // warp reduce (3 independent chains)
        #pragma unroll
        for (int off = 16; off > 0; off >>= 1) {
            s1 += __shfl_xor_sync(0xFFFFFFFFu, s1, off);
            s2 += __shfl_xor_sync(0xFFFFFFFFu, s2, off);
            s3 += __shfl_xor_sync(0xFFFFFFFFu, s3, off);
        }

        const int par = i & 1;
        if (lane == 0) {
            red[par][0][wid] = s1;
            red[par][1][wid] = s2;
            red[par][2][wid] = s3;
        }
        __syncthreads();   // B: partials ready; slot fully consumed
        float t1 = 0.f, t2 = 0.f, t3 = 0.f;
        #pragma unroll
        for (int w = 0; w < 8; w++) {
            t1 += red[par][0][w];
            t2 += red[par][1][w];
            t3 += red[par][2][w];
        }

        const float rs3     = rs * rs * rs;
        const float pd_var  = -0.5f * t1 * rs3;
        const float pd_mean = -t2 * rs + pd_var * (-2.0f * inv_d) * t3;
        const float coef    = pd_var * (2.0f * inv_d);
        const float cmean   = pd_mean * inv_d;

        float ov[8];
        #pragma unroll
        for (int k = 0; k < 8; k++) {
            const float pdxl = dyv[k] * gv[k];
            ov[k] = fmaf(pdxl, rs, fmaf(coef, xh[k], cmean)) + dsv[k];
            ag[k] = fmaf(dyv[k] * xh[k], rs, ag[k]);
            ab[k] += dyv[k];
        }

        const size_t base = (size_t)row * HF;
        __stcs((float4*)(out + base + c0), make_float4(ov[0], ov[1], ov[2], ov[3]));
        __stcs((float4*)(out + base + c1), make_float4(ov[4], ov[5], ov[6], ov[7]));
    }

    // flush dgamma/dbeta partials: 444 CTAs * 4096 atomics -> negligible
    float* gout = out + (size_t)ROWS * HF;
    float* bout = gout + HF;
    #pragma unroll
    for (int k = 0; k < 4; k++) {
        atomicAdd(gout + c0 + k, ag[k]);
        atomicAdd(gout + c1 + k, ag[4 + k]);
        atomicAdd(bout + c0 + k, ab[k]);
        atomicAdd(bout + c1 + k, ab[4 + k]);
    }
}

extern "C" void kernel_launch(void* const* d_in, const int* in_sizes, int n_in,
                              void* d_out, int out_size) {
    const float* dy    = (const float*)d_in[0];
    const float* x1    = (const float*)d_in[1];
    const float* x2    = (const float*)d_in[2];
    const float* rstd  = (const float*)d_in[3];
    const float* mean  = (const float*)d_in[4];
    const float* gamma = (const float*)d_in[5];
    const float* dsum  = (const float*)d_in[6];
    float* out = (float*)d_out;

    static bool attr_set = false;
    if (!attr_set) {
        cudaFuncSetAttribute(ln_bwd_kernel,
                             cudaFuncAttributeMaxDynamicSharedMemorySize, DYN_SMEM);
        attr_set = true;
    }

    zero_param_grads<<<(2 * HF + 255) / 256, 256>>>(out);
    ln_bwd_kernel<<<GRID, THREADS, DYN_SMEM>>>(dy, x1, x2, rstd, mean, gamma, dsum, out);
}